// round 16
// baseline (speedup 1.0000x reference)
#include <cuda_runtime.h>
#include <cstdint>

#define HDIM 4096
#define EXP  64
#define BM   128
#define BK   32
#define GCAP 8192
#define SCAP 6144   // smem candidate cap in selectf
#define LCAP 24     // per-CTA per-expert gather buffer

typedef unsigned long long ull;

// ---------------------------------------------------------------------------
// Device globals
// ---------------------------------------------------------------------------
__device__ float    g_thresh[EXP];
__device__ unsigned g_hist0[EXP * 64];
__device__ unsigned g_b0[EXP];
__device__ unsigned g_remk[EXP];
__device__ int      g_cand_n[EXP];
__device__ unsigned g_cand[EXP][GCAP];
__device__ unsigned g_cand2[EXP][GCAP];

__device__ __forceinline__ unsigned sortable(float f) {
    unsigned u = __float_as_uint(f);
    return u ^ ((u & 0x80000000u) ? 0xFFFFFFFFu : 0x80000000u);
}

// Dynamic smem (gemm): xs[32][130] floats | wsd[32][64] ull | hist 4096 u32
#define XS_FLOATS 4160
#define WSD_ULLS  2048
#define GEMM_SMEM ((XS_FLOATS + 2 * WSD_ULLS + 4096) * 4)   // 49408 B

// ---------------------------------------------------------------------------
// Kernel 1: logits = x @ W, exact fp32 (R12 body; W staged pre-duplicated
// so the per-k mov.b64 packs disappear). Accumulation k-ascending per
// output -> bit-identical to R1/R12. Fused top-6-bit histogram epilogue.
// ---------------------------------------------------------------------------
__global__ __launch_bounds__(256, 3) void gemm_kernel(const float* __restrict__ x,
                                                      const float* __restrict__ W,
                                                      float* __restrict__ logits) {
    extern __shared__ float smem[];
    float (*xs)[130] = (float(*)[130])smem;                   // [k][row]
    ull  (*wsd)[EXP] = (ull(*)[EXP])(smem + XS_FLOATS);       // [k][col] dup (w,w)
    unsigned* shist  = (unsigned*)(smem + XS_FLOATS + 2 * WSD_ULLS);

    const int tid  = threadIdx.x;
    const int row0 = blockIdx.x * BM;
    const int cg   = tid & 15;   // cols cg*4 .. cg*4+3
    const int rg   = tid >> 4;   // rows rg*8 .. rg*8+7

#pragma unroll
    for (int i = 0; i < 16; ++i) shist[tid + i * 256] = 0;

    ull acc[4][4];  // [col j][row-pair ip]
#pragma unroll
    for (int j = 0; j < 4; ++j)
#pragma unroll
        for (int ip = 0; ip < 4; ++ip) acc[j][ip] = 0ULL;

    const int lr = tid >> 3;          // x load row within 32-row pass
    const int lc = (tid & 7) * 4;     // x load col (float4)
    const int wk = tid >> 4;          // W row (first half; +16 second)
    const int wc = (tid & 15) * 4;    // W col quad

    for (int k0 = 0; k0 < HDIM; k0 += BK) {
        // stage x tile [BM x BK] -> xs[k][row]
#pragma unroll
        for (int p = 0; p < 4; ++p) {
            int r = lr + p * 32;
            float4 v = *(const float4*)(x + (size_t)(row0 + r) * HDIM + k0 + lc);
            xs[lc + 0][r] = v.x; xs[lc + 1][r] = v.y;
            xs[lc + 2][r] = v.z; xs[lc + 3][r] = v.w;
        }
        // stage W tile [BK x 64], duplicated (w,w)
#pragma unroll
        for (int p = 0; p < 2; ++p) {
            int r = wk + p * 16;
            float4 v = *(const float4*)(W + (size_t)(k0 + r) * EXP + wc);
            ull d0, d1, d2, d3;
            asm("mov.b64 %0, {%1, %1};" : "=l"(d0) : "r"(__float_as_uint(v.x)));
            asm("mov.b64 %0, {%1, %1};" : "=l"(d1) : "r"(__float_as_uint(v.y)));
            asm("mov.b64 %0, {%1, %1};" : "=l"(d2) : "r"(__float_as_uint(v.z)));
            asm("mov.b64 %0, {%1, %1};" : "=l"(d3) : "r"(__float_as_uint(v.w)));
            *(ulonglong2*)&wsd[r][wc]     = make_ulonglong2(d0, d1);
            *(ulonglong2*)&wsd[r][wc + 2] = make_ulonglong2(d2, d3);
        }
        __syncthreads();

#pragma unroll
        for (int k = 0; k < BK; ++k) {
            ulonglong2 q0 = *(const ulonglong2*)&wsd[k][cg * 4];
            ulonglong2 q1 = *(const ulonglong2*)&wsd[k][cg * 4 + 2];
            ull b2[4] = {q0.x, q0.y, q1.x, q1.y};
            ull a2[4];
#pragma unroll
            for (int ip = 0; ip < 4; ++ip)
                a2[ip] = *(const ull*)&xs[k][rg * 8 + ip * 2];
#pragma unroll
            for (int j = 0; j < 4; ++j)
#pragma unroll
                for (int ip = 0; ip < 4; ++ip)
                    asm("fma.rn.f32x2 %0, %1, %2, %0;"
                        : "+l"(acc[j][ip]) : "l"(a2[ip]), "l"(b2[j]));
        }
        __syncthreads();
    }

    // writeback + fused histogram
#pragma unroll
    for (int ip = 0; ip < 4; ++ip) {
        float lo[4], hi[4];
#pragma unroll
        for (int j = 0; j < 4; ++j) {
            lo[j] = __uint_as_float((unsigned)(acc[j][ip] & 0xFFFFFFFFULL));
            hi[j] = __uint_as_float((unsigned)(acc[j][ip] >> 32));
            int e = cg * 4 + j;
            atomicAdd(&shist[e * 64 + (sortable(lo[j]) >> 26)], 1u);
            atomicAdd(&shist[e * 64 + (sortable(hi[j]) >> 26)], 1u);
        }
        int r = row0 + rg * 8 + ip * 2;
        *(float4*)(logits + (size_t)r * EXP + cg * 4) =
            make_float4(lo[0], lo[1], lo[2], lo[3]);
        *(float4*)(logits + (size_t)(r + 1) * EXP + cg * 4) =
            make_float4(hi[0], hi[1], hi[2], hi[3]);
    }
    __syncthreads();
#pragma unroll
    for (int i = 0; i < 16; ++i) {
        unsigned c = shist[tid + i * 256];
        if (c) atomicAdd(&g_hist0[tid + i * 256], c);
    }
}

// ---------------------------------------------------------------------------
// Kernel 3: pick top bucket + residual k per expert
// ---------------------------------------------------------------------------
__global__ void bucket_kernel(int k) {
    int e = threadIdx.x;   // 64 threads
    unsigned remk = (unsigned)k, cum = 0;
    int b = 63;
    for (; b > 0; --b) {
        unsigned h = g_hist0[e * 64 + b];
        if (cum + h >= remk) break;
        cum += h;
    }
    g_b0[e]   = (unsigned)b;
    g_remk[e] = remk - cum;
}

// ---------------------------------------------------------------------------
// Kernel 4: gather with CTA-level smem aggregation (few global atomics)
// ---------------------------------------------------------------------------
__global__ __launch_bounds__(256) void gather_kernel(const float* __restrict__ logits) {
    __shared__ unsigned sb0[EXP];
    __shared__ unsigned buf[EXP][LCAP];
    __shared__ int      cnt[EXP];
    if (threadIdx.x < EXP) { sb0[threadIdx.x] = g_b0[threadIdx.x]; cnt[threadIdx.x] = 0; }
    __syncthreads();
    const int t = blockIdx.x * 256 + threadIdx.x;   // token row
    const float4* row = (const float4*)(logits + (size_t)t * EXP);
#pragma unroll
    for (int q = 0; q < 16; ++q) {
        float4 v = row[q];
        float vv[4] = {v.x, v.y, v.z, v.w};
#pragma unroll
        for (int m = 0; m < 4; ++m) {
            int e = q * 4 + m;
            unsigned u = sortable(vv[m]);
            if ((u >> 26) == sb0[e]) {
                int i = atomicAdd(&cnt[e], 1);
                if (i < LCAP) buf[e][i] = u;
                else {                                   // rare overflow: direct
                    int g = atomicAdd(&g_cand_n[e], 1);
                    if (g < GCAP) g_cand[e][g] = u;
                }
            }
        }
    }
    __syncthreads();
    if (threadIdx.x < EXP) {
        int e = threadIdx.x;
        int n = cnt[e]; if (n > LCAP) n = LCAP;
        if (n > 0) {
            int base = atomicAdd(&g_cand_n[e], n);
            for (int i = 0; i < n; ++i) {
                int g = base + i;
                if (g < GCAP) g_cand[e][g] = buf[e][i];
            }
        }
    }
}

// ---------------------------------------------------------------------------
// Kernel 5: per-expert k-th largest. Candidates copied to smem; parallel
// suffix-sum bin selection. Global scanning fallback if overflow.
// ---------------------------------------------------------------------------
__global__ __launch_bounds__(256) void selectf_kernel(const float* __restrict__ logits,
                                                      int N) {
    __shared__ unsigned sc[2][SCAP];
    __shared__ unsigned hist[256];
    __shared__ unsigned ssum[257];
    __shared__ unsigned s_bv, s_remk, s_prefix, s_n2;
    const int e   = blockIdx.x;
    const int tid = threadIdx.x;
    const unsigned b0 = g_b0[e];
    const int cn = g_cand_n[e];
    const int SH[4] = {18, 10, 2, 0};
    const unsigned MK[4] = {255, 255, 255, 3};

    if (tid == 0) { s_remk = g_remk[e]; s_prefix = 0; }
    __syncthreads();

    if (cn <= SCAP) {
        for (int j = tid; j < cn; j += 256) sc[0][j] = g_cand[e][j];
        __syncthreads();
        int n = cn, cur = 0;
        for (int p = 0; p < 4; ++p) {
            const int sh = SH[p]; const unsigned mk = MK[p];
            hist[tid] = 0;
            __syncthreads();
            for (int j = tid; j < n; j += 256) atomicAdd(&hist[(sc[cur][j] >> sh) & mk], 1u);
            __syncthreads();
            // parallel suffix sum over 256 bins
            ssum[tid] = (tid <= (int)mk) ? hist[tid] : 0u;
            if (tid == 0) ssum[256] = 0;
            __syncthreads();
#pragma unroll
            for (int st = 1; st < 256; st <<= 1) {
                unsigned add = (tid + st < 256) ? ssum[tid + st] : 0u;
                __syncthreads();
                ssum[tid] += add;
                __syncthreads();
            }
            {
                unsigned remk = s_remk;
                if (ssum[tid] >= remk && ssum[tid + 1] < remk) {
                    s_bv = (unsigned)tid;
                    s_remk = remk - ssum[tid + 1];
                }
            }
            if (tid == 0) s_n2 = 0;
            __syncthreads();
            if (tid == 0) s_prefix |= s_bv << sh;
            if (p < 3) {
                unsigned bv = s_bv;
                for (int j = tid; j < n; j += 256) {
                    unsigned key = sc[cur][j];
                    if (((key >> sh) & mk) == bv) { unsigned q = atomicAdd(&s_n2, 1u); sc[1 - cur][q] = key; }
                }
                __syncthreads();
                n = (int)s_n2; cur ^= 1;
            }
            __syncthreads();
        }
        if (tid == 0) {
            unsigned key = (b0 << 26) | s_prefix;
            unsigned bits = (key & 0x80000000u) ? (key ^ 0x80000000u) : ~key;
            g_thresh[e] = __uint_as_float(bits);
        }
    } else {
        // fallback: scanning radix over the full column with growing prefix
        unsigned pmask = 0xFC000000u;
        if (tid == 0) s_prefix = b0 << 26;
        __syncthreads();
        for (int p = 0; p < 4; ++p) {
            const int sh = SH[p]; const unsigned mk = MK[p];
            hist[tid] = 0;
            __syncthreads();
            const unsigned pre = s_prefix;
            for (int i = tid; i < N; i += 256) {
                unsigned u = sortable(logits[(size_t)i * EXP + e]);
                if ((u & pmask) == pre) atomicAdd(&hist[(u >> sh) & mk], 1u);
            }
            __syncthreads();
            if (tid == 0) {
                unsigned remk = s_remk, cum = 0;
                int b = (int)mk;
                for (; b > 0; --b) { unsigned h = hist[b]; if (cum + h >= remk) break; cum += h; }
                s_prefix = pre | (((unsigned)b) << sh); s_remk = remk - cum;
            }
            pmask |= mk << sh;
            __syncthreads();
        }
        if (tid == 0) {
            unsigned key = s_prefix;
            unsigned bits = (key & 0x80000000u) ? (key ^ 0x80000000u) : ~key;
            g_thresh[e] = __uint_as_float(bits);
        }
    }
}

// ---------------------------------------------------------------------------
// Kernel 6: conflict resolution + fallback argmax. One warp per token.
// ---------------------------------------------------------------------------
__global__ __launch_bounds__(256) void assign_kernel(const float* __restrict__ logits,
                                                     float* __restrict__ out_w,
                                                     float* __restrict__ out_i,
                                                     int N) {
    const int gwarp = (int)((blockIdx.x * (size_t)blockDim.x + threadIdx.x) >> 5);
    const int lane  = threadIdx.x & 31;
    if (gwarp >= N) return;

    const float NEG_INF = __int_as_float(0xff800000);
    float2 v = *(const float2*)(logits + (size_t)gwarp * EXP + lane * 2);
    float t0 = g_thresh[lane * 2];
    float t1 = g_thresh[lane * 2 + 1];

    float cs = NEG_INF; int ci = 127;                  // claimed best
    if (v.x >= t0)             { cs = v.x; ci = lane * 2; }
    if (v.y >= t1 && v.y > cs) { cs = v.y; ci = lane * 2 + 1; }

    float fs = v.x; int fi = lane * 2;                 // fallback argmax
    if (v.y > fs) { fs = v.y; fi = lane * 2 + 1; }

#pragma unroll
    for (int off = 16; off; off >>= 1) {
        float os = __shfl_xor_sync(0xFFFFFFFFu, cs, off);
        int   oi = __shfl_xor_sync(0xFFFFFFFFu, ci, off);
        if (os > cs || (os == cs && oi < ci)) { cs = os; ci = oi; }
        float ofs = __shfl_xor_sync(0xFFFFFFFFu, fs, off);
        int   ofi = __shfl_xor_sync(0xFFFFFFFFu, fi, off);
        if (ofs > fs || (ofs == fs && ofi < fi)) { fs = ofs; fi = ofi; }
    }

    if (lane == 0) {
        float w; int e;
        if (ci < EXP) { w = cs; e = ci; }
        else          { w = fs; e = fi; }
        out_w[gwarp] = w;
        out_i[gwarp] = (float)e;
    }
}

// ---------------------------------------------------------------------------
// Output layout: [0,N) weights | [N,2N) indices (float) | [2N, 2N+N*E) logits
// ---------------------------------------------------------------------------
extern "C" void kernel_launch(void* const* d_in, const int* in_sizes, int n_in,
                              void* d_out, int out_size) {
    const float* x = (const float*)d_in[0];
    const float* W = (const float*)d_in[1];
    const int N = in_sizes[0] / HDIM;   // 32768

    float* out    = (float*)d_out;
    float* out_w  = out;
    float* out_i  = out + N;
    float* logits = out + 2 * (size_t)N;

    int k = N / EXP;
    if (k < 1) k = 1;
    if (k > N) k = N;

    static int attr_set = 0;
    if (!attr_set) {
        cudaFuncSetAttribute(gemm_kernel, cudaFuncAttributeMaxDynamicSharedMemorySize, GEMM_SMEM);
        attr_set = 1;
    }

    void* p;
    cudaGetSymbolAddress(&p, g_hist0);  cudaMemsetAsync(p, 0, EXP * 64 * sizeof(unsigned));
    cudaGetSymbolAddress(&p, g_cand_n); cudaMemsetAsync(p, 0, EXP * sizeof(int));

    gemm_kernel<<<N / BM, 256, GEMM_SMEM>>>(x, W, logits);
    bucket_kernel<<<1, 64>>>(k);
    gather_kernel<<<N / 256, 256>>>(logits);
    selectf_kernel<<<EXP, 256>>>(logits, N);
    assign_kernel<<<(int)(((size_t)N * 32 + 255) / 256), 256>>>(logits, out_w, out_i, N);
}

// round 17
// speedup vs baseline: 1.6757x; 1.6757x over previous
#include <cuda_runtime.h>
#include <cstdint>

#define HDIM 4096
#define EXP  64
#define BM   128
#define BK   32
#define GCAP 8192
#define SCAP 6144   // smem candidate cap in selectf
#define LCAP 24     // per-CTA per-expert gather buffer

typedef unsigned long long ull;

// ---------------------------------------------------------------------------
// Device globals
// ---------------------------------------------------------------------------
__device__ float    g_thresh[EXP];
__device__ unsigned g_hist0[EXP * 64];
__device__ unsigned g_b0[EXP];
__device__ unsigned g_remk[EXP];
__device__ int      g_cand_n[EXP];
__device__ unsigned g_cand[EXP][GCAP];

__device__ __forceinline__ unsigned sortable(float f) {
    unsigned u = __float_as_uint(f);
    return u ^ ((u & 0x80000000u) ? 0xFFFFFFFFu : 0x80000000u);
}

// ---------------------------------------------------------------------------
// Kernel 1: logits[N,64] = x[N,4096] @ W[4096,64], exact fp32 accumulate.
// R12's proven compute body (435us GEMM) verbatim; only addition is the
// fused top-6-bit histogram in the epilogue (outputs already in registers).
// Accumulation k-ascending per output -> bit-identical results.
// ---------------------------------------------------------------------------
__global__ __launch_bounds__(256, 3) void gemm_kernel(const float* __restrict__ x,
                                                      const float* __restrict__ W,
                                                      float* __restrict__ logits) {
    __shared__ float xs[BK][BM + 2];   // k-major x tile (row pairs contiguous)
    __shared__ float ws[BK][EXP];
    __shared__ unsigned shist[EXP * 64];

    const int tid  = threadIdx.x;
    const int row0 = blockIdx.x * BM;
    const int cg   = tid & 15;   // cols cg*4 .. cg*4+3
    const int rg   = tid >> 4;   // rows rg*8 .. rg*8+7

#pragma unroll
    for (int i = 0; i < 16; ++i) shist[tid + i * 256] = 0;

    ull acc[4][4];  // [col j][row-pair ip]; lanes = (row 2ip, row 2ip+1)
#pragma unroll
    for (int j = 0; j < 4; ++j)
#pragma unroll
        for (int ip = 0; ip < 4; ++ip) acc[j][ip] = 0ULL;

    const int lr = tid >> 3;          // load row within 32-row pass
    const int lc = (tid & 7) * 4;     // load col (float4)

    for (int k0 = 0; k0 < HDIM; k0 += BK) {
        // stage x tile [BM x BK] -> xs[k][row]
#pragma unroll
        for (int p = 0; p < 4; ++p) {
            int r = lr + p * 32;
            float4 v = *(const float4*)(x + (size_t)(row0 + r) * HDIM + k0 + lc);
            xs[lc + 0][r] = v.x; xs[lc + 1][r] = v.y;
            xs[lc + 2][r] = v.z; xs[lc + 3][r] = v.w;
        }
        // stage W tile [BK x 64]
#pragma unroll
        for (int p = 0; p < 2; ++p) {
            int idx = tid + p * 256;
            int r = idx >> 4;
            int c = (idx & 15) * 4;
            *(float4*)&ws[r][c] = *(const float4*)(W + (size_t)(k0 + r) * EXP + c);
        }
        __syncthreads();

#pragma unroll
        for (int k = 0; k < BK; ++k) {
            float4 bv = *(const float4*)&ws[k][cg * 4];
            ull b2[4];
            asm("mov.b64 %0, {%1, %1};" : "=l"(b2[0]) : "r"(__float_as_uint(bv.x)));
            asm("mov.b64 %0, {%1, %1};" : "=l"(b2[1]) : "r"(__float_as_uint(bv.y)));
            asm("mov.b64 %0, {%1, %1};" : "=l"(b2[2]) : "r"(__float_as_uint(bv.z)));
            asm("mov.b64 %0, {%1, %1};" : "=l"(b2[3]) : "r"(__float_as_uint(bv.w)));
            ull a2[4];
#pragma unroll
            for (int ip = 0; ip < 4; ++ip)
                a2[ip] = *(const ull*)&xs[k][rg * 8 + ip * 2];
#pragma unroll
            for (int j = 0; j < 4; ++j)
#pragma unroll
                for (int ip = 0; ip < 4; ++ip)
                    asm("fma.rn.f32x2 %0, %1, %2, %0;"
                        : "+l"(acc[j][ip]) : "l"(a2[ip]), "l"(b2[j]));
        }
        __syncthreads();
    }

    // writeback + fused histogram: 8 rows x 4 cols per thread
#pragma unroll
    for (int ip = 0; ip < 4; ++ip) {
        float lo[4], hi[4];
#pragma unroll
        for (int j = 0; j < 4; ++j) {
            lo[j] = __uint_as_float((unsigned)(acc[j][ip] & 0xFFFFFFFFULL));
            hi[j] = __uint_as_float((unsigned)(acc[j][ip] >> 32));
            int e = cg * 4 + j;
            atomicAdd(&shist[e * 64 + (sortable(lo[j]) >> 26)], 1u);
            atomicAdd(&shist[e * 64 + (sortable(hi[j]) >> 26)], 1u);
        }
        int r = row0 + rg * 8 + ip * 2;
        *(float4*)(logits + (size_t)r * EXP + cg * 4) =
            make_float4(lo[0], lo[1], lo[2], lo[3]);
        *(float4*)(logits + (size_t)(r + 1) * EXP + cg * 4) =
            make_float4(hi[0], hi[1], hi[2], hi[3]);
    }
    __syncthreads();
#pragma unroll
    for (int i = 0; i < 16; ++i) {
        unsigned c = shist[tid + i * 256];
        if (c) atomicAdd(&g_hist0[tid + i * 256], c);
    }
}

// ---------------------------------------------------------------------------
// Kernel 2: pick top bucket + residual k per expert
// ---------------------------------------------------------------------------
__global__ void bucket_kernel(int k) {
    int e = threadIdx.x;   // 64 threads
    unsigned remk = (unsigned)k, cum = 0;
    int b = 63;
    for (; b > 0; --b) {
        unsigned h = g_hist0[e * 64 + b];
        if (cum + h >= remk) break;
        cum += h;
    }
    g_b0[e]   = (unsigned)b;
    g_remk[e] = remk - cum;
}

// ---------------------------------------------------------------------------
// Kernel 3: gather with CTA-level smem aggregation (few global atomics)
// ---------------------------------------------------------------------------
__global__ __launch_bounds__(256) void gather_kernel(const float* __restrict__ logits) {
    __shared__ unsigned sb0[EXP];
    __shared__ unsigned buf[EXP][LCAP];
    __shared__ int      cnt[EXP];
    if (threadIdx.x < EXP) { sb0[threadIdx.x] = g_b0[threadIdx.x]; cnt[threadIdx.x] = 0; }
    __syncthreads();
    const int t = blockIdx.x * 256 + threadIdx.x;   // token row
    const float4* row = (const float4*)(logits + (size_t)t * EXP);
#pragma unroll
    for (int q = 0; q < 16; ++q) {
        float4 v = row[q];
        float vv[4] = {v.x, v.y, v.z, v.w};
#pragma unroll
        for (int m = 0; m < 4; ++m) {
            int e = q * 4 + m;
            unsigned u = sortable(vv[m]);
            if ((u >> 26) == sb0[e]) {
                int i = atomicAdd(&cnt[e], 1);
                if (i < LCAP) buf[e][i] = u;
                else {                                   // rare overflow: direct
                    int g = atomicAdd(&g_cand_n[e], 1);
                    if (g < GCAP) g_cand[e][g] = u;
                }
            }
        }
    }
    __syncthreads();
    if (threadIdx.x < EXP) {
        int e = threadIdx.x;
        int n = cnt[e]; if (n > LCAP) n = LCAP;
        if (n > 0) {
            int base = atomicAdd(&g_cand_n[e], n);
            for (int i = 0; i < n; ++i) {
                int g = base + i;
                if (g < GCAP) g_cand[e][g] = buf[e][i];
            }
        }
    }
}

// ---------------------------------------------------------------------------
// Kernel 4: per-expert k-th largest. Candidates in smem; parallel
// suffix-sum bin selection (race-fenced). Scanning fallback on overflow.
// ---------------------------------------------------------------------------
__global__ __launch_bounds__(256) void selectf_kernel(const float* __restrict__ logits,
                                                      int N) {
    __shared__ unsigned sc[2][SCAP];
    __shared__ unsigned hist[256];
    __shared__ unsigned ssum[257];
    __shared__ unsigned s_bv, s_remk, s_prefix, s_n2;
    const int e   = blockIdx.x;
    const int tid = threadIdx.x;
    const unsigned b0 = g_b0[e];
    const int cn = g_cand_n[e];
    const int SH[4] = {18, 10, 2, 0};
    const unsigned MK[4] = {255, 255, 255, 3};

    if (tid == 0) { s_remk = g_remk[e]; s_prefix = 0; }
    __syncthreads();

    if (cn <= SCAP) {
        for (int j = tid; j < cn; j += 256) sc[0][j] = g_cand[e][j];
        __syncthreads();
        int n = cn, cur = 0;
        for (int p = 0; p < 4; ++p) {
            const int sh = SH[p]; const unsigned mk = MK[p];
            hist[tid] = 0;
            __syncthreads();
            for (int j = tid; j < n; j += 256) atomicAdd(&hist[(sc[cur][j] >> sh) & mk], 1u);
            __syncthreads();
            // parallel suffix sum over 256 bins
            ssum[tid] = (tid <= (int)mk) ? hist[tid] : 0u;
            if (tid == 0) ssum[256] = 0;
            __syncthreads();
#pragma unroll
            for (int st = 1; st < 256; st <<= 1) {
                unsigned add = (tid + st < 256) ? ssum[tid + st] : 0u;
                __syncthreads();
                ssum[tid] += add;
                __syncthreads();
            }
            const unsigned remk_snap = s_remk;
            __syncthreads();                       // all reads precede winner's write
            if (ssum[tid] >= remk_snap && ssum[tid + 1] < remk_snap) {
                s_bv = (unsigned)tid;
                s_remk = remk_snap - ssum[tid + 1];
            }
            if (tid == 0) s_n2 = 0;
            __syncthreads();
            if (tid == 0) s_prefix |= s_bv << sh;
            if (p < 3) {
                unsigned bv = s_bv;
                for (int j = tid; j < n; j += 256) {
                    unsigned key = sc[cur][j];
                    if (((key >> sh) & mk) == bv) { unsigned q = atomicAdd(&s_n2, 1u); sc[1 - cur][q] = key; }
                }
                __syncthreads();
                n = (int)s_n2; cur ^= 1;
            }
            __syncthreads();
        }
        if (tid == 0) {
            unsigned key = (b0 << 26) | s_prefix;
            unsigned bits = (key & 0x80000000u) ? (key ^ 0x80000000u) : ~key;
            g_thresh[e] = __uint_as_float(bits);
        }
    } else {
        // fallback: scanning radix over the full column with growing prefix
        unsigned pmask = 0xFC000000u;
        if (tid == 0) s_prefix = b0 << 26;
        __syncthreads();
        for (int p = 0; p < 4; ++p) {
            const int sh = SH[p]; const unsigned mk = MK[p];
            hist[tid] = 0;
            __syncthreads();
            const unsigned pre = s_prefix;
            for (int i = tid; i < N; i += 256) {
                unsigned u = sortable(logits[(size_t)i * EXP + e]);
                if ((u & pmask) == pre) atomicAdd(&hist[(u >> sh) & mk], 1u);
            }
            __syncthreads();
            if (tid == 0) {
                unsigned remk = s_remk, cum = 0;
                int b = (int)mk;
                for (; b > 0; --b) { unsigned h = hist[b]; if (cum + h >= remk) break; cum += h; }
                s_prefix = pre | (((unsigned)b) << sh); s_remk = remk - cum;
            }
            pmask |= mk << sh;
            __syncthreads();
        }
        if (tid == 0) {
            unsigned key = s_prefix;
            unsigned bits = (key & 0x80000000u) ? (key ^ 0x80000000u) : ~key;
            g_thresh[e] = __uint_as_float(bits);
        }
    }
}

// ---------------------------------------------------------------------------
// Kernel 5: conflict resolution + fallback argmax. One warp per token.
// ---------------------------------------------------------------------------
__global__ __launch_bounds__(256) void assign_kernel(const float* __restrict__ logits,
                                                     float* __restrict__ out_w,
                                                     float* __restrict__ out_i,
                                                     int N) {
    const int gwarp = (int)((blockIdx.x * (size_t)blockDim.x + threadIdx.x) >> 5);
    const int lane  = threadIdx.x & 31;
    if (gwarp >= N) return;

    const float NEG_INF = __int_as_float(0xff800000);
    float2 v = *(const float2*)(logits + (size_t)gwarp * EXP + lane * 2);
    float t0 = g_thresh[lane * 2];
    float t1 = g_thresh[lane * 2 + 1];

    float cs = NEG_INF; int ci = 127;                  // claimed best
    if (v.x >= t0)             { cs = v.x; ci = lane * 2; }
    if (v.y >= t1 && v.y > cs) { cs = v.y; ci = lane * 2 + 1; }

    float fs = v.x; int fi = lane * 2;                 // fallback argmax
    if (v.y > fs) { fs = v.y; fi = lane * 2 + 1; }

#pragma unroll
    for (int off = 16; off; off >>= 1) {
        float os = __shfl_xor_sync(0xFFFFFFFFu, cs, off);
        int   oi = __shfl_xor_sync(0xFFFFFFFFu, ci, off);
        if (os > cs || (os == cs && oi < ci)) { cs = os; ci = oi; }
        float ofs = __shfl_xor_sync(0xFFFFFFFFu, fs, off);
        int   ofi = __shfl_xor_sync(0xFFFFFFFFu, fi, off);
        if (ofs > fs || (ofs == fs && ofi < fi)) { fs = ofs; fi = ofi; }
    }

    if (lane == 0) {
        float w; int e;
        if (ci < EXP) { w = cs; e = ci; }
        else          { w = fs; e = fi; }
        out_w[gwarp] = w;
        out_i[gwarp] = (float)e;
    }
}

// ---------------------------------------------------------------------------
// Output layout: [0,N) weights | [N,2N) indices (float) | [2N, 2N+N*E) logits
// ---------------------------------------------------------------------------
extern "C" void kernel_launch(void* const* d_in, const int* in_sizes, int n_in,
                              void* d_out, int out_size) {
    const float* x = (const float*)d_in[0];
    const float* W = (const float*)d_in[1];
    const int N = in_sizes[0] / HDIM;   // 32768

    float* out    = (float*)d_out;
    float* out_w  = out;
    float* out_i  = out + N;
    float* logits = out + 2 * (size_t)N;

    int k = N / EXP;
    if (k < 1) k = 1;
    if (k > N) k = N;

    void* p;
    cudaGetSymbolAddress(&p, g_hist0);  cudaMemsetAsync(p, 0, EXP * 64 * sizeof(unsigned));
    cudaGetSymbolAddress(&p, g_cand_n); cudaMemsetAsync(p, 0, EXP * sizeof(int));

    gemm_kernel<<<N / BM, 256>>>(x, W, logits);
    bucket_kernel<<<1, 64>>>(k);
    gather_kernel<<<N / 256, 256>>>(logits);
    selectf_kernel<<<EXP, 256>>>(logits, N);
    assign_kernel<<<(int)(((size_t)N * 32 + 255) / 256), 256>>>(logits, out_w, out_i, N);
}